// round 15
// baseline (speedup 1.0000x reference)
#include <cuda_runtime.h>
#include <cuda_bf16.h>
#include <math.h>
#include <stdint.h>

#define LSEQ   4096
#define DMODEL 1024
typedef __nv_bfloat16 bf16;

// ---------------- static device scratch ------------------------------------
__device__ bf16 g_x0[LSEQ * DMODEL], g_x1[LSEQ * DMODEL];
__device__ bf16 g_z0[LSEQ * DMODEL], g_z1[LSEQ * DMODEL];
__device__ bf16 g_Wq0[DMODEL * DMODEL], g_Wq1[DMODEL * DMODEL];
__device__ bf16 g_Wk0[DMODEL * DMODEL], g_Wk1[DMODEL * DMODEL];
__device__ bf16 g_Wv0[DMODEL * DMODEL], g_Wv1[DMODEL * DMODEL];
__device__ bf16 g_Q0[LSEQ * DMODEL], g_Q1[LSEQ * DMODEL];
__device__ bf16 g_K0[LSEQ * DMODEL], g_K1[LSEQ * DMODEL];
__device__ bf16 g_VT0[DMODEL * LSEQ], g_VT1[DMODEL * LSEQ];
__device__ float g_S[(size_t)LSEQ * LSEQ];
__device__ bf16 g_P0[(size_t)LSEQ * LSEQ], g_P1[(size_t)LSEQ * LSEQ];

// ---------------- helpers ---------------------------------------------------
__device__ __forceinline__ uint32_t s2u(const void* p) {
    uint32_t a;
    asm("{ .reg .u64 t; cvta.to.shared.u64 t, %1; cvt.u32.u64 %0, t; }" : "=r"(a) : "l"(p));
    return a;
}
__device__ __forceinline__ uint32_t pk(bf16 a, bf16 b) {
    return (uint32_t)__bfloat16_as_ushort(a) | ((uint32_t)__bfloat16_as_ushort(b) << 16);
}
__device__ __forceinline__ void split2(float v, bf16& h, bf16& l) {
    h = __float2bfloat16(v);
    l = __float2bfloat16(v - __bfloat162float(h));
}
__device__ __forceinline__ void cp16(uint32_t s, const void* g) {
    asm volatile("cp.async.cg.shared.global [%0], [%1], 16;" :: "r"(s), "l"(g));
}
__device__ __forceinline__ void cp_commit() { asm volatile("cp.async.commit_group;"); }
template <int N> __device__ __forceinline__ void cp_wait() {
    asm volatile("cp.async.wait_group %0;" :: "n"(N));
}
__device__ __forceinline__ void ldsm_x4(uint32_t r[4], uint32_t addr) {
    asm volatile("ldmatrix.sync.aligned.m8n8.x4.shared.b16 {%0,%1,%2,%3}, [%4];"
                 : "=r"(r[0]), "=r"(r[1]), "=r"(r[2]), "=r"(r[3]) : "r"(addr));
}
__device__ __forceinline__ void mma16816(float d[4], const uint32_t a[4],
                                         const uint32_t b0, const uint32_t b1) {
    asm volatile(
        "mma.sync.aligned.m16n8k16.row.col.f32.bf16.bf16.f32 "
        "{%0,%1,%2,%3}, {%4,%5,%6,%7}, {%8,%9}, {%0,%1,%2,%3};"
        : "+f"(d[0]), "+f"(d[1]), "+f"(d[2]), "+f"(d[3])
        : "r"(a[0]), "r"(a[1]), "r"(a[2]), "r"(a[3]), "r"(b0), "r"(b1));
}

// ---------------- prep kernels ----------------------------------------------
__global__ void split_f32(const float* __restrict__ x, const float* __restrict__ z) {
    int b = blockIdx.x;
    const float* in; bf16 *o0, *o1;
    if (b < 4096) { in = x; o0 = g_x0; o1 = g_x1; }
    else          { in = z; o0 = g_z0; o1 = g_z1; b -= 4096; }
    int i = (b * 256 + threadIdx.x) * 4;
    float4 v = *(const float4*)(in + i);
    bf16 h0, l0, h1, l1, h2, l2, h3, l3;
    split2(v.x, h0, l0); split2(v.y, h1, l1);
    split2(v.z, h2, l2); split2(v.w, h3, l3);
    *(uint2*)(o0 + i) = make_uint2(pk(h0, h1), pk(h2, h3));
    *(uint2*)(o1 + i) = make_uint2(pk(l0, l1), pk(l2, l3));
}

__global__ void tsplit_w(const float* __restrict__ Wq, const float* __restrict__ Wk,
                         const float* __restrict__ Wv) {
    __shared__ float t[32][33];
    const float* W = (blockIdx.z == 0) ? Wq : (blockIdx.z == 1) ? Wk : Wv;
    bf16* O0 = (blockIdx.z == 0) ? g_Wq0 : (blockIdx.z == 1) ? g_Wk0 : g_Wv0;
    bf16* O1 = (blockIdx.z == 0) ? g_Wq1 : (blockIdx.z == 1) ? g_Wk1 : g_Wv1;
    int k0 = blockIdx.y * 32, n0 = blockIdx.x * 32;
    int tx = threadIdx.x, ty = threadIdx.y;
#pragma unroll
    for (int i = 0; i < 4; i++)
        t[ty + 8 * i][tx] = W[(size_t)(k0 + ty + 8 * i) * DMODEL + n0 + tx];
    __syncthreads();
#pragma unroll
    for (int i = 0; i < 4; i++) {
        float v = t[tx][ty + 8 * i];           // = W[k0+tx][n0+ty+8i]
        bf16 h, l; split2(v, h, l);
        size_t o = (size_t)(n0 + ty + 8 * i) * DMODEL + k0 + tx;
        O0[o] = h; O1[o] = l;
    }
}

// ---------------- mma.sync GEMM core: C[M,N] = sum_k A[m,k] B[n,k] ----------
// CTA tile 128x64, K-stage 32, 128 threads = 4 warps in 2x2 (warp tile 64x32).
// TRIPLE-buffered cp.async (group waited on was issued 2 stages ago), ONE
// barrier per stage, issue-ahead before the MMA burst. 80B conflict-free pitch.
// 2 CTAs/SM.
#define GT 128
#define RP 80u
#define STG 30720u                  // Ah(10240)+Al(10240)+Bh(5120)+Bl(5120)
#define OFF_AL 10240u
#define OFF_BH 20480u
#define OFF_BL 25600u
#define SMEM_SZ (3u * STG)          // 92160

__device__ __forceinline__ void gemm_core(
    const bf16* __restrict__ A0, const bf16* __restrict__ A1,
    const bf16* __restrict__ B0, const bf16* __restrict__ B1,
    int Ktot, int kstart, int m0, int n0,
    float* __restrict__ Cf, bf16* __restrict__ C0, bf16* __restrict__ C1,
    const float* __restrict__ bias, int bias_mode, int ldc)
{
    extern __shared__ char smem[];
    const uint32_t dataB = s2u(smem);
    const int tid = threadIdx.x;
    const int lane = tid & 31, wid = tid >> 5;
    const int wm = (wid >> 1) * 64;
    const int wn = (wid & 1) * 32;

    const int S = (Ktot - kstart) >> 5;     // K-stage = 32

    // Coalesced producer: per tile, chunks = rows x 4x16B; 4 consecutive
    // threads cover 64 consecutive bytes of one row.
    auto issue = [&](int s) {
        const uint32_t st = dataB + (uint32_t)(s % 3) * STG;
        const size_t kbase = (size_t)kstart + ((size_t)s << 5);
#pragma unroll
        for (int t = 0; t < 4; t++) {        // A tiles: 512 chunks
            int chunk = tid + t * 128;
            int row = chunk >> 2, cc = chunk & 3;
            uint32_t so = (uint32_t)row * RP + (uint32_t)cc * 16;
            size_t go = kbase + (size_t)cc * 8;
            cp16(st + so,          A0 + (size_t)(m0 + row) * Ktot + go);
            cp16(st + OFF_AL + so, A1 + (size_t)(m0 + row) * Ktot + go);
        }
#pragma unroll
        for (int t = 0; t < 2; t++) {        // B tiles: 256 chunks
            int chunk = tid + t * 128;
            int row = chunk >> 2, cc = chunk & 3;
            uint32_t so = (uint32_t)row * RP + (uint32_t)cc * 16;
            size_t go = kbase + (size_t)cc * 8;
            cp16(st + OFF_BH + so, B0 + (size_t)(n0 + row) * Ktot + go);
            cp16(st + OFF_BL + so, B1 + (size_t)(n0 + row) * Ktot + go);
        }
        cp_commit();
    };

    float acc[4][4][4];
#pragma unroll
    for (int i = 0; i < 4; i++)
#pragma unroll
        for (int j = 0; j < 4; j++)
#pragma unroll
            for (int q = 0; q < 4; q++) acc[i][j][q] = 0.0f;

    issue(0);
    issue(1);

    const int a_r  = (lane & 15);
    const int a_c  = (lane >> 4);                      // 16B chunk select
    const int b_r  = (lane & 7) + ((lane >> 4) << 3);
    const int b_c  = ((lane >> 3) & 1);

    for (int s = 0; s < S; s++) {
        // Own group s was issued 2 stages ago -> wait is nearly always free.
        cp_wait<1>();
        // Publishes all threads' stage-s data AND guarantees everyone finished
        // consuming stage s-1, so buffer (s+2)%3 == (s-1)%3 is reusable.
        __syncthreads();
        if (s + 2 < S) issue(s + 2); else cp_commit();

        const uint32_t st = dataB + (uint32_t)(s % 3) * STG;
        const uint32_t tAh = st, tAl = st + OFF_AL, tBh = st + OFF_BH, tBl = st + OFF_BL;

#pragma unroll
        for (int ks = 0; ks < 2; ks++) {     // two k16 blocks per stage
            uint32_t ah[4][4], al[4][4];
#pragma unroll
            for (int i = 0; i < 4; i++) {
                int r = wm + 16 * i + a_r;
                uint32_t so = (uint32_t)r * RP + (uint32_t)(ks * 2 + a_c) * 16;
                ldsm_x4(ah[i], tAh + so);
                ldsm_x4(al[i], tAl + so);
            }
            uint32_t bh[4][2], bl[4][2];
#pragma unroll
            for (int j2 = 0; j2 < 2; j2++) {
                int r = wn + 16 * j2 + b_r;
                uint32_t so = (uint32_t)r * RP + (uint32_t)(ks * 2 + b_c) * 16;
                uint32_t t0[4], t1[4];
                ldsm_x4(t0, tBh + so);
                ldsm_x4(t1, tBl + so);
                bh[2*j2][0] = t0[0]; bh[2*j2][1] = t0[1];
                bh[2*j2+1][0] = t0[2]; bh[2*j2+1][1] = t0[3];
                bl[2*j2][0] = t1[0]; bl[2*j2][1] = t1[1];
                bl[2*j2+1][0] = t1[2]; bl[2*j2+1][1] = t1[3];
            }
#pragma unroll
            for (int i = 0; i < 4; i++)
#pragma unroll
                for (int j = 0; j < 4; j++) {
                    mma16816(acc[i][j], ah[i], bh[j][0], bh[j][1]);
                    mma16816(acc[i][j], ah[i], bl[j][0], bl[j][1]);
                    mma16816(acc[i][j], al[i], bh[j][0], bh[j][1]);
                }
        }
    }

    const int rbase = m0 + wm + (lane >> 2);
    const int cbase = n0 + wn + 2 * (lane & 3);
#pragma unroll
    for (int i = 0; i < 4; i++) {
        const int mlo = rbase + 16 * i, mhi = mlo + 8;
        float blo = 0.0f, bhi = 0.0f;
        if (bias_mode == 2) { blo = bias[mlo]; bhi = bias[mhi]; }
#pragma unroll
        for (int j = 0; j < 4; j++) {
            const int c = cbase + 8 * j;
            float d0 = acc[i][j][0], d1 = acc[i][j][1];
            float d2 = acc[i][j][2], d3 = acc[i][j][3];
            if (bias_mode == 1) {
                float b0 = __ldg(bias + c), b1 = __ldg(bias + c + 1);
                d0 += b0; d1 += b1; d2 += b0; d3 += b1;
            } else if (bias_mode == 2) {
                d0 += blo; d1 += blo; d2 += bhi; d3 += bhi;
            }
            if (C0) {
                bf16 h0, l0, h1, l1;
                split2(d0, h0, l0); split2(d1, h1, l1);
                *(uint32_t*)(C0 + (size_t)mlo * ldc + c) = pk(h0, h1);
                *(uint32_t*)(C1 + (size_t)mlo * ldc + c) = pk(l0, l1);
                split2(d2, h0, l0); split2(d3, h1, l1);
                *(uint32_t*)(C0 + (size_t)mhi * ldc + c) = pk(h0, h1);
                *(uint32_t*)(C1 + (size_t)mhi * ldc + c) = pk(l0, l1);
            } else {
                *(float2*)(Cf + (size_t)mlo * ldc + c) = make_float2(d0, d1);
                *(float2*)(Cf + (size_t)mhi * ldc + c) = make_float2(d2, d3);
            }
        }
    }
}

// Generic wrapper (QK tri grid / PV)
__global__ __launch_bounds__(GT, 2)
void gemm_bf16x3(const bf16* __restrict__ A0, const bf16* __restrict__ A1,
                 const bf16* __restrict__ B0, const bf16* __restrict__ B1,
                 int Ktot, int kstart_rb, int tri_mode,
                 float* __restrict__ Cf, bf16* __restrict__ C0, bf16* __restrict__ C1,
                 const float* __restrict__ bias, int bias_mode, int ldc)
{
    int m0, n0;
    if (tri_mode) {
        int bid = blockIdx.x, rb = 0;
        while (bid >= 64 - 2 * rb) { bid -= 64 - 2 * rb; rb++; }
        m0 = rb * 128; n0 = (2 * rb + bid) * 64;
    } else {
        m0 = blockIdx.y * 128; n0 = blockIdx.x * 64;
    }
    gemm_core(A0, A1, B0, B1, Ktot, kstart_rb ? m0 : 0, m0, n0,
              Cf, C0, C1, bias, bias_mode, ldc);
}

// Fused QKV projection: one 1536-CTA launch.
__global__ __launch_bounds__(GT, 2)
void qkv_kernel(const float* __restrict__ bq, const float* __restrict__ bk,
                const float* __restrict__ bv)
{
    int bid = blockIdx.x;
    if (bid < 512) {
        int m0 = (bid >> 4) * 128, n0 = (bid & 15) * 64;
        gemm_core(g_x0, g_x1, g_Wq0, g_Wq1, DMODEL, 0, m0, n0,
                  nullptr, g_Q0, g_Q1, bq, 1, DMODEL);
    } else if (bid < 1024) {
        bid -= 512;
        int m0 = (bid >> 4) * 128, n0 = (bid & 15) * 64;
        gemm_core(g_z0, g_z1, g_Wk0, g_Wk1, DMODEL, 0, m0, n0,
                  nullptr, g_K0, g_K1, bk, 1, DMODEL);
    } else {
        bid -= 1024;
        int m0 = (bid >> 6) * 128, n0 = (bid & 63) * 64;
        gemm_core(g_Wv0, g_Wv1, g_z0, g_z1, DMODEL, 0, m0, n0,
                  nullptr, g_VT0, g_VT1, bv, 2, LSEQ);
    }
}

// ---------------- softmax + P split -----------------------------------------
__global__ void softmax_kernel() {
    __shared__ float srow[LSEQ];
    __shared__ float red[8];
    __shared__ float bc;
    const int i = blockIdx.x;
    const float* row = g_S + (size_t)i * LSEQ;
    const int tid = threadIdx.x;
    const float sc = 0.03125f;

    float m = -INFINITY;
    for (int j = i + tid; j < LSEQ; j += 256) { float v = row[j]; srow[j] = v; m = fmaxf(m, v); }
#pragma unroll
    for (int o = 16; o; o >>= 1) m = fmaxf(m, __shfl_xor_sync(~0u, m, o));
    if ((tid & 31) == 0) red[tid >> 5] = m;
    __syncthreads();
    if (tid < 32) {
        float v = (tid < 8) ? red[tid] : -INFINITY;
#pragma unroll
        for (int o = 4; o; o >>= 1) v = fmaxf(v, __shfl_xor_sync(~0u, v, o));
        if (tid == 0) bc = v;
    }
    __syncthreads();
    m = bc;
    __syncthreads();

    float s = 0.0f;
    for (int j = i + tid; j < LSEQ; j += 256) {
        float e = __expf((srow[j] - m) * sc);
        srow[j] = e; s += e;
    }
#pragma unroll
    for (int o = 16; o; o >>= 1) s += __shfl_xor_sync(~0u, s, o);
    if ((tid & 31) == 0) red[tid >> 5] = s;
    __syncthreads();
    if (tid < 32) {
        float v = (tid < 8) ? red[tid] : 0.0f;
#pragma unroll
        for (int o = 4; o; o >>= 1) v += __shfl_xor_sync(~0u, v, o);
        if (tid == 0) bc = v;
    }
    __syncthreads();
    const float inv = 1.0f / bc;

    const int rowstart = i & ~127;
    bf16* p0 = g_P0 + (size_t)i * LSEQ;
    bf16* p1 = g_P1 + (size_t)i * LSEQ;
    for (int j = rowstart + tid; j < LSEQ; j += 256) {
        float v = (j < i) ? 0.0f : srow[j] * inv;
        bf16 h, l; split2(v, h, l);
        p0[j] = h; p1[j] = l;
    }
}

// ---------------- launch -----------------------------------------------------
extern "C" void kernel_launch(void* const* d_in, const int* in_sizes, int n_in,
                              void* d_out, int out_size)
{
    const float* x  = (const float*)d_in[0];
    const float* z  = (const float*)d_in[1];
    const float* Wq = (const float*)d_in[2];
    const float* bq = (const float*)d_in[3];
    const float* Wk = (const float*)d_in[4];
    const float* bk = (const float*)d_in[5];
    const float* Wv = (const float*)d_in[6];
    const float* bv = (const float*)d_in[7];
    float* out = (float*)d_out;

    cudaFuncSetAttribute(gemm_bf16x3, cudaFuncAttributeMaxDynamicSharedMemorySize, SMEM_SZ);
    cudaFuncSetAttribute(qkv_kernel, cudaFuncAttributeMaxDynamicSharedMemorySize, SMEM_SZ);

    bf16 *q0, *q1, *k0, *k1, *vt0, *vt1, *p0, *p1;
    float* S;
    cudaGetSymbolAddress((void**)&q0, g_Q0);  cudaGetSymbolAddress((void**)&q1, g_Q1);
    cudaGetSymbolAddress((void**)&k0, g_K0);  cudaGetSymbolAddress((void**)&k1, g_K1);
    cudaGetSymbolAddress((void**)&vt0, g_VT0); cudaGetSymbolAddress((void**)&vt1, g_VT1);
    cudaGetSymbolAddress((void**)&p0, g_P0);  cudaGetSymbolAddress((void**)&p1, g_P1);
    cudaGetSymbolAddress((void**)&S, g_S);

    split_f32<<<8192, 256>>>(x, z);
    tsplit_w<<<dim3(32, 32, 3), dim3(32, 8)>>>(Wq, Wk, Wv);

    // Q, K, VT projections fused in one launch (1536 CTAs)
    qkv_kernel<<<1536, GT, SMEM_SZ>>>(bq, bk, bv);

    // S = Q @ K^T  (compact triangular grid: 1056 live 128x64 blocks)
    gemm_bf16x3<<<dim3(1056, 1), GT, SMEM_SZ>>>(q0, q1, k0, k1, DMODEL, 0, 1,
                                                S, nullptr, nullptr, nullptr, 0, LSEQ);
    softmax_kernel<<<LSEQ, 256>>>();
    // O = P @ V  (k starts at row-block diagonal; longest-K blocks first)
    gemm_bf16x3<<<dim3(16, 32), GT, SMEM_SZ>>>(p0, p1, vt0, vt1, LSEQ, 1, 0,
                                               out, nullptr, nullptr, nullptr, 0, DMODEL);
}

// round 16
// speedup vs baseline: 1.3478x; 1.3478x over previous
#include <cuda_runtime.h>
#include <cuda_bf16.h>
#include <math.h>
#include <stdint.h>

#define LSEQ   4096
#define DMODEL 1024
typedef __nv_bfloat16 bf16;

// ---------------- static device scratch ------------------------------------
__device__ bf16 g_x0[LSEQ * DMODEL], g_x1[LSEQ * DMODEL];
__device__ bf16 g_z0[LSEQ * DMODEL], g_z1[LSEQ * DMODEL];
__device__ bf16 g_Wq0[DMODEL * DMODEL], g_Wq1[DMODEL * DMODEL];
__device__ bf16 g_Wk0[DMODEL * DMODEL], g_Wk1[DMODEL * DMODEL];
__device__ bf16 g_Wv0[DMODEL * DMODEL], g_Wv1[DMODEL * DMODEL];
__device__ bf16 g_Q0[LSEQ * DMODEL], g_Q1[LSEQ * DMODEL];
__device__ bf16 g_K0[LSEQ * DMODEL], g_K1[LSEQ * DMODEL];
__device__ bf16 g_VT0[DMODEL * LSEQ], g_VT1[DMODEL * LSEQ];
__device__ float g_S[(size_t)LSEQ * LSEQ];
__device__ bf16 g_P0[(size_t)LSEQ * LSEQ], g_P1[(size_t)LSEQ * LSEQ];

// ---------------- helpers ---------------------------------------------------
__device__ __forceinline__ uint32_t s2u(const void* p) {
    uint32_t a;
    asm("{ .reg .u64 t; cvta.to.shared.u64 t, %1; cvt.u32.u64 %0, t; }" : "=r"(a) : "l"(p));
    return a;
}
__device__ __forceinline__ uint32_t pk(bf16 a, bf16 b) {
    return (uint32_t)__bfloat16_as_ushort(a) | ((uint32_t)__bfloat16_as_ushort(b) << 16);
}
__device__ __forceinline__ void split2(float v, bf16& h, bf16& l) {
    h = __float2bfloat16(v);
    l = __float2bfloat16(v - __bfloat162float(h));
}
__device__ __forceinline__ void cp16(uint32_t s, const void* g) {
    asm volatile("cp.async.cg.shared.global [%0], [%1], 16;" :: "r"(s), "l"(g));
}
__device__ __forceinline__ void cp_commit() { asm volatile("cp.async.commit_group;"); }
template <int N> __device__ __forceinline__ void cp_wait() {
    asm volatile("cp.async.wait_group %0;" :: "n"(N));
}
__device__ __forceinline__ void ldsm_x4(uint32_t r[4], uint32_t addr) {
    asm volatile("ldmatrix.sync.aligned.m8n8.x4.shared.b16 {%0,%1,%2,%3}, [%4];"
                 : "=r"(r[0]), "=r"(r[1]), "=r"(r[2]), "=r"(r[3]) : "r"(addr));
}
__device__ __forceinline__ void mma16816(float d[4], const uint32_t a[4],
                                         const uint32_t b0, const uint32_t b1) {
    asm volatile(
        "mma.sync.aligned.m16n8k16.row.col.f32.bf16.bf16.f32 "
        "{%0,%1,%2,%3}, {%4,%5,%6,%7}, {%8,%9}, {%0,%1,%2,%3};"
        : "+f"(d[0]), "+f"(d[1]), "+f"(d[2]), "+f"(d[3])
        : "r"(a[0]), "r"(a[1]), "r"(a[2]), "r"(a[3]), "r"(b0), "r"(b1));
}
// swizzled byte offset inside a (rows x 128-byte) tile
__device__ __forceinline__ uint32_t swz(int row, int kbyte) {
    return (uint32_t)row * 128 + ((((uint32_t)kbyte >> 4) ^ ((uint32_t)row & 7)) << 4);
}

// ---------------- prep kernels ----------------------------------------------
__global__ void split_f32(const float* __restrict__ x, const float* __restrict__ z) {
    int b = blockIdx.x;
    const float* in; bf16 *o0, *o1;
    if (b < 4096) { in = x; o0 = g_x0; o1 = g_x1; }
    else          { in = z; o0 = g_z0; o1 = g_z1; b -= 4096; }
    int i = (b * 256 + threadIdx.x) * 4;
    float4 v = *(const float4*)(in + i);
    bf16 h0, l0, h1, l1, h2, l2, h3, l3;
    split2(v.x, h0, l0); split2(v.y, h1, l1);
    split2(v.z, h2, l2); split2(v.w, h3, l3);
    *(uint2*)(o0 + i) = make_uint2(pk(h0, h1), pk(h2, h3));
    *(uint2*)(o1 + i) = make_uint2(pk(l0, l1), pk(l2, l3));
}

__global__ void tsplit_w(const float* __restrict__ Wq, const float* __restrict__ Wk,
                         const float* __restrict__ Wv) {
    __shared__ float t[32][33];
    const float* W = (blockIdx.z == 0) ? Wq : (blockIdx.z == 1) ? Wk : Wv;
    bf16* O0 = (blockIdx.z == 0) ? g_Wq0 : (blockIdx.z == 1) ? g_Wk0 : g_Wv0;
    bf16* O1 = (blockIdx.z == 0) ? g_Wq1 : (blockIdx.z == 1) ? g_Wk1 : g_Wv1;
    int k0 = blockIdx.y * 32, n0 = blockIdx.x * 32;
    int tx = threadIdx.x, ty = threadIdx.y;
#pragma unroll
    for (int i = 0; i < 4; i++)
        t[ty + 8 * i][tx] = W[(size_t)(k0 + ty + 8 * i) * DMODEL + n0 + tx];
    __syncthreads();
#pragma unroll
    for (int i = 0; i < 4; i++) {
        float v = t[tx][ty + 8 * i];           // = W[k0+tx][n0+ty+8i]
        bf16 h, l; split2(v, h, l);
        size_t o = (size_t)(n0 + ty + 8 * i) * DMODEL + k0 + tx;
        O0[o] = h; O1[o] = l;
    }
}

// ---------------- mma.sync GEMM core: C[M,N] = sum_k A[m,k] B[n,k] ----------
// CTA tile 128x64, K-stage 64, 128 threads = 4 warps in 2x2 (warp tile 64x32).
// Double-buffered cp.async, 2 CTAs/SM.  (R14 configuration — proven best.)
#define GT 128
#define STG 49152u
#define OFF_AL 16384u
#define OFF_BH 32768u
#define OFF_BL 40960u
#define SMEM_SZ (2u * STG)

__device__ __forceinline__ void gemm_core(
    const bf16* __restrict__ A0, const bf16* __restrict__ A1,
    const bf16* __restrict__ B0, const bf16* __restrict__ B1,
    int Ktot, int kstart, int m0, int n0,
    float* __restrict__ Cf, bf16* __restrict__ C0, bf16* __restrict__ C1,
    const float* __restrict__ bias, int bias_mode, int ldc)
{
    extern __shared__ char smem[];
    const uint32_t dataB = s2u(smem);
    const int tid = threadIdx.x;
    const int lane = tid & 31, wid = tid >> 5;
    const int wm = (wid >> 1) * 64;
    const int wn = (wid & 1) * 32;

    const int S = (Ktot - kstart) >> 6;

    auto issue = [&](int s) {
        const uint32_t st = dataB + (uint32_t)(s & 1) * STG;
        const size_t kbase = (size_t)kstart + ((size_t)s << 6);
#pragma unroll
        for (int t = 0; t < 8; t++) {
            int chunk = tid + t * 128;
            int row = chunk >> 3, cc = chunk & 7;
            uint32_t so = swz(row, cc << 4);
            size_t go = kbase + (size_t)cc * 8;
            cp16(st + so,          A0 + (size_t)(m0 + row) * Ktot + go);
            cp16(st + OFF_AL + so, A1 + (size_t)(m0 + row) * Ktot + go);
        }
#pragma unroll
        for (int t = 0; t < 4; t++) {
            int chunk = tid + t * 128;
            int row = chunk >> 3, cc = chunk & 7;
            uint32_t so = swz(row, cc << 4);
            size_t go = kbase + (size_t)cc * 8;
            cp16(st + OFF_BH + so, B0 + (size_t)(n0 + row) * Ktot + go);
            cp16(st + OFF_BL + so, B1 + (size_t)(n0 + row) * Ktot + go);
        }
        cp_commit();
    };

    float acc[4][4][4];
#pragma unroll
    for (int i = 0; i < 4; i++)
#pragma unroll
        for (int j = 0; j < 4; j++)
#pragma unroll
            for (int q = 0; q < 4; q++) acc[i][j][q] = 0.0f;

    issue(0);
    if (S > 1) issue(1); else cp_commit();

    const int a_r  = (lane & 15);
    const int a_kb = (lane >> 4) << 4;
    const int b_r  = (lane & 7) + ((lane >> 4) << 3);
    const int b_kb = ((lane >> 3) & 1) << 4;

    for (int s = 0; s < S; s++) {
        cp_wait<1>();
        __syncthreads();
        const uint32_t st = dataB + (uint32_t)(s & 1) * STG;
        const uint32_t tAh = st, tAl = st + OFF_AL, tBh = st + OFF_BH, tBl = st + OFF_BL;

#pragma unroll
        for (int ks = 0; ks < 4; ks++) {
            const int kb = ks << 5;
            uint32_t ah[4][4], al[4][4];
#pragma unroll
            for (int i = 0; i < 4; i++) {
                int r = wm + 16 * i + a_r;
                uint32_t so = swz(r, kb + a_kb);
                ldsm_x4(ah[i], tAh + so);
                ldsm_x4(al[i], tAl + so);
            }
            uint32_t bh[4][2], bl[4][2];
#pragma unroll
            for (int j2 = 0; j2 < 2; j2++) {
                int r = wn + 16 * j2 + b_r;
                uint32_t so = swz(r, kb + b_kb);
                uint32_t t0[4], t1[4];
                ldsm_x4(t0, tBh + so);
                ldsm_x4(t1, tBl + so);
                bh[2*j2][0] = t0[0]; bh[2*j2][1] = t0[1];
                bh[2*j2+1][0] = t0[2]; bh[2*j2+1][1] = t0[3];
                bl[2*j2][0] = t1[0]; bl[2*j2][1] = t1[1];
                bl[2*j2+1][0] = t1[2]; bl[2*j2+1][1] = t1[3];
            }
#pragma unroll
            for (int i = 0; i < 4; i++)
#pragma unroll
                for (int j = 0; j < 4; j++) {
                    mma16816(acc[i][j], ah[i], bh[j][0], bh[j][1]);
                    mma16816(acc[i][j], ah[i], bl[j][0], bl[j][1]);
                    mma16816(acc[i][j], al[i], bh[j][0], bh[j][1]);
                }
        }
        __syncthreads();
        if (s + 2 < S) issue(s + 2); else cp_commit();
    }

    const int rbase = m0 + wm + (lane >> 2);
    const int cbase = n0 + wn + 2 * (lane & 3);
#pragma unroll
    for (int i = 0; i < 4; i++) {
        const int mlo = rbase + 16 * i, mhi = mlo + 8;
        float blo = 0.0f, bhi = 0.0f;
        if (bias_mode == 2) { blo = bias[mlo]; bhi = bias[mhi]; }
#pragma unroll
        for (int j = 0; j < 4; j++) {
            const int c = cbase + 8 * j;
            float d0 = acc[i][j][0], d1 = acc[i][j][1];
            float d2 = acc[i][j][2], d3 = acc[i][j][3];
            if (bias_mode == 1) {
                float b0 = __ldg(bias + c), b1 = __ldg(bias + c + 1);
                d0 += b0; d1 += b1; d2 += b0; d3 += b1;
            } else if (bias_mode == 2) {
                d0 += blo; d1 += blo; d2 += bhi; d3 += bhi;
            }
            if (C0) {
                bf16 h0, l0, h1, l1;
                split2(d0, h0, l0); split2(d1, h1, l1);
                *(uint32_t*)(C0 + (size_t)mlo * ldc + c) = pk(h0, h1);
                *(uint32_t*)(C1 + (size_t)mlo * ldc + c) = pk(l0, l1);
                split2(d2, h0, l0); split2(d3, h1, l1);
                *(uint32_t*)(C0 + (size_t)mhi * ldc + c) = pk(h0, h1);
                *(uint32_t*)(C1 + (size_t)mhi * ldc + c) = pk(l0, l1);
            } else {
                *(float2*)(Cf + (size_t)mlo * ldc + c) = make_float2(d0, d1);
                *(float2*)(Cf + (size_t)mhi * ldc + c) = make_float2(d2, d3);
            }
        }
    }
}

// Generic wrapper (QK tri grid / PV)
__global__ __launch_bounds__(GT, 2)
void gemm_bf16x3(const bf16* __restrict__ A0, const bf16* __restrict__ A1,
                 const bf16* __restrict__ B0, const bf16* __restrict__ B1,
                 int Ktot, int kstart_rb, int tri_mode,
                 float* __restrict__ Cf, bf16* __restrict__ C0, bf16* __restrict__ C1,
                 const float* __restrict__ bias, int bias_mode, int ldc)
{
    int m0, n0;
    if (tri_mode) {
        int bid = blockIdx.x, rb = 0;
        while (bid >= 64 - 2 * rb) { bid -= 64 - 2 * rb; rb++; }
        m0 = rb * 128; n0 = (2 * rb + bid) * 64;
    } else {
        m0 = blockIdx.y * 128; n0 = blockIdx.x * 64;
    }
    gemm_core(A0, A1, B0, B1, Ktot, kstart_rb ? m0 : 0, m0, n0,
              Cf, C0, C1, bias, bias_mode, ldc);
}

// Fused QKV projection: one 1536-CTA launch.
__global__ __launch_bounds__(GT, 2)
void qkv_kernel(const float* __restrict__ bq, const float* __restrict__ bk,
                const float* __restrict__ bv)
{
    int bid = blockIdx.x;
    if (bid < 512) {
        int m0 = (bid >> 4) * 128, n0 = (bid & 15) * 64;
        gemm_core(g_x0, g_x1, g_Wq0, g_Wq1, DMODEL, 0, m0, n0,
                  nullptr, g_Q0, g_Q1, bq, 1, DMODEL);
    } else if (bid < 1024) {
        bid -= 512;
        int m0 = (bid >> 4) * 128, n0 = (bid & 15) * 64;
        gemm_core(g_z0, g_z1, g_Wk0, g_Wk1, DMODEL, 0, m0, n0,
                  nullptr, g_K0, g_K1, bk, 1, DMODEL);
    } else {
        bid -= 1024;
        int m0 = (bid >> 6) * 128, n0 = (bid & 63) * 64;
        gemm_core(g_Wv0, g_Wv1, g_z0, g_z1, DMODEL, 0, m0, n0,
                  nullptr, g_VT0, g_VT1, bv, 2, LSEQ);
    }
}

// ---------------- softmax + P split (512 threads) ----------------------------
__global__ void softmax_kernel() {
    __shared__ float srow[LSEQ];
    __shared__ float red[16];
    __shared__ float bc;
    const int i = blockIdx.x;
    const float* row = g_S + (size_t)i * LSEQ;
    const int tid = threadIdx.x;
    const float sc = 0.03125f;

    float m = -INFINITY;
    for (int j = i + tid; j < LSEQ; j += 512) { float v = row[j]; srow[j] = v; m = fmaxf(m, v); }
#pragma unroll
    for (int o = 16; o; o >>= 1) m = fmaxf(m, __shfl_xor_sync(~0u, m, o));
    if ((tid & 31) == 0) red[tid >> 5] = m;
    __syncthreads();
    if (tid < 32) {
        float v = (tid < 16) ? red[tid] : -INFINITY;
#pragma unroll
        for (int o = 8; o; o >>= 1) v = fmaxf(v, __shfl_xor_sync(~0u, v, o));
        if (tid == 0) bc = v;
    }
    __syncthreads();
    m = bc;
    __syncthreads();

    float s = 0.0f;
    for (int j = i + tid; j < LSEQ; j += 512) {
        float e = __expf((srow[j] - m) * sc);
        srow[j] = e; s += e;
    }
#pragma unroll
    for (int o = 16; o; o >>= 1) s += __shfl_xor_sync(~0u, s, o);
    if ((tid & 31) == 0) red[tid >> 5] = s;
    __syncthreads();
    if (tid < 32) {
        float v = (tid < 16) ? red[tid] : 0.0f;
#pragma unroll
        for (int o = 8; o; o >>= 1) v += __shfl_xor_sync(~0u, v, o);
        if (tid == 0) bc = v;
    }
    __syncthreads();
    const float inv = 1.0f / bc;

    const int rowstart = i & ~127;
    bf16* p0 = g_P0 + (size_t)i * LSEQ;
    bf16* p1 = g_P1 + (size_t)i * LSEQ;
    for (int j = rowstart + tid; j < LSEQ; j += 512) {
        float v = (j < i) ? 0.0f : srow[j] * inv;
        bf16 h, l; split2(v, h, l);
        p0[j] = h; p1[j] = l;
    }
}

// ---------------- launch -----------------------------------------------------
extern "C" void kernel_launch(void* const* d_in, const int* in_sizes, int n_in,
                              void* d_out, int out_size)
{
    const float* x  = (const float*)d_in[0];
    const float* z  = (const float*)d_in[1];
    const float* Wq = (const float*)d_in[2];
    const float* bq = (const float*)d_in[3];
    const float* Wk = (const float*)d_in[4];
    const float* bk = (const float*)d_in[5];
    const float* Wv = (const float*)d_in[6];
    const float* bv = (const float*)d_in[7];
    float* out = (float*)d_out;

    cudaFuncSetAttribute(gemm_bf16x3, cudaFuncAttributeMaxDynamicSharedMemorySize, SMEM_SZ);
    cudaFuncSetAttribute(qkv_kernel, cudaFuncAttributeMaxDynamicSharedMemorySize, SMEM_SZ);

    bf16 *q0, *q1, *k0, *k1, *vt0, *vt1, *p0, *p1;
    float* S;
    cudaGetSymbolAddress((void**)&q0, g_Q0);  cudaGetSymbolAddress((void**)&q1, g_Q1);
    cudaGetSymbolAddress((void**)&k0, g_K0);  cudaGetSymbolAddress((void**)&k1, g_K1);
    cudaGetSymbolAddress((void**)&vt0, g_VT0); cudaGetSymbolAddress((void**)&vt1, g_VT1);
    cudaGetSymbolAddress((void**)&p0, g_P0);  cudaGetSymbolAddress((void**)&p1, g_P1);
    cudaGetSymbolAddress((void**)&S, g_S);

    split_f32<<<8192, 256>>>(x, z);
    tsplit_w<<<dim3(32, 32, 3), dim3(32, 8)>>>(Wq, Wk, Wv);

    // Q, K, VT projections fused in one launch (1536 CTAs)
    qkv_kernel<<<1536, GT, SMEM_SZ>>>(bq, bk, bv);

    // S = Q @ K^T  (compact triangular grid: 1056 live 128x64 blocks)
    gemm_bf16x3<<<dim3(1056, 1), GT, SMEM_SZ>>>(q0, q1, k0, k1, DMODEL, 0, 1,
                                                S, nullptr, nullptr, nullptr, 0, LSEQ);
    softmax_kernel<<<LSEQ, 512>>>();
    // O = P @ V  (k starts at row-block diagonal; longest-K blocks first)
    gemm_bf16x3<<<dim3(16, 32), GT, SMEM_SZ>>>(p0, p1, vt0, vt1, LSEQ, 1, 0,
                                               out, nullptr, nullptr, nullptr, 0, DMODEL);
}

// round 17
// speedup vs baseline: 1.4008x; 1.0393x over previous
#include <cuda_runtime.h>
#include <cuda_bf16.h>
#include <math.h>
#include <stdint.h>

#define LSEQ   4096
#define DMODEL 1024
typedef __nv_bfloat16 bf16;

// ---------------- static device scratch ------------------------------------
__device__ bf16 g_x0[LSEQ * DMODEL], g_x1[LSEQ * DMODEL];
__device__ bf16 g_z0[LSEQ * DMODEL], g_z1[LSEQ * DMODEL];
__device__ bf16 g_Wq0[DMODEL * DMODEL], g_Wq1[DMODEL * DMODEL];  // untransposed split
__device__ bf16 g_Wk0[DMODEL * DMODEL], g_Wk1[DMODEL * DMODEL];  // untransposed split
__device__ bf16 g_Wv0[DMODEL * DMODEL], g_Wv1[DMODEL * DMODEL];  // transposed split
__device__ bf16 g_MT0[DMODEL * DMODEL], g_MT1[DMODEL * DMODEL];  // (WqWk^T)^T split
__device__ bf16 g_G0[LSEQ * DMODEL], g_G1[LSEQ * DMODEL];        // x @ M split
__device__ bf16 g_VT0[DMODEL * LSEQ], g_VT1[DMODEL * LSEQ];
__device__ float g_S[(size_t)LSEQ * LSEQ];
__device__ bf16 g_P0[(size_t)LSEQ * LSEQ], g_P1[(size_t)LSEQ * LSEQ];
__device__ float g_w[DMODEL];   // Wk @ bq
__device__ float g_c[LSEQ];     // z @ (Wk @ bq)  — column bias surviving softmax

// ---------------- helpers ---------------------------------------------------
__device__ __forceinline__ uint32_t s2u(const void* p) {
    uint32_t a;
    asm("{ .reg .u64 t; cvta.to.shared.u64 t, %1; cvt.u32.u64 %0, t; }" : "=r"(a) : "l"(p));
    return a;
}
__device__ __forceinline__ uint32_t pk(bf16 a, bf16 b) {
    return (uint32_t)__bfloat16_as_ushort(a) | ((uint32_t)__bfloat16_as_ushort(b) << 16);
}
__device__ __forceinline__ void split2(float v, bf16& h, bf16& l) {
    h = __float2bfloat16(v);
    l = __float2bfloat16(v - __bfloat162float(h));
}
__device__ __forceinline__ void cp16(uint32_t s, const void* g) {
    asm volatile("cp.async.cg.shared.global [%0], [%1], 16;" :: "r"(s), "l"(g));
}
__device__ __forceinline__ void cp_commit() { asm volatile("cp.async.commit_group;"); }
template <int N> __device__ __forceinline__ void cp_wait() {
    asm volatile("cp.async.wait_group %0;" :: "n"(N));
}
__device__ __forceinline__ void ldsm_x4(uint32_t r[4], uint32_t addr) {
    asm volatile("ldmatrix.sync.aligned.m8n8.x4.shared.b16 {%0,%1,%2,%3}, [%4];"
                 : "=r"(r[0]), "=r"(r[1]), "=r"(r[2]), "=r"(r[3]) : "r"(addr));
}
__device__ __forceinline__ void mma16816(float d[4], const uint32_t a[4],
                                         const uint32_t b0, const uint32_t b1) {
    asm volatile(
        "mma.sync.aligned.m16n8k16.row.col.f32.bf16.bf16.f32 "
        "{%0,%1,%2,%3}, {%4,%5,%6,%7}, {%8,%9}, {%0,%1,%2,%3};"
        : "+f"(d[0]), "+f"(d[1]), "+f"(d[2]), "+f"(d[3])
        : "r"(a[0]), "r"(a[1]), "r"(a[2]), "r"(a[3]), "r"(b0), "r"(b1));
}
__device__ __forceinline__ uint32_t swz(int row, int kbyte) {
    return (uint32_t)row * 128 + ((((uint32_t)kbyte >> 4) ^ ((uint32_t)row & 7)) << 4);
}

// ---------------- prep kernels ----------------------------------------------
// Elementwise splits: x (blocks 0..4095), z (4096..8191), Wq (8192..9215),
// Wk (9216..10239).
__global__ void split_f32(const float* __restrict__ x, const float* __restrict__ z,
                          const float* __restrict__ Wq, const float* __restrict__ Wk) {
    int b = blockIdx.x;
    const float* in; bf16 *o0, *o1;
    if (b < 4096)      { in = x;  o0 = g_x0;  o1 = g_x1; }
    else if (b < 8192) { in = z;  o0 = g_z0;  o1 = g_z1;  b -= 4096; }
    else if (b < 9216) { in = Wq; o0 = g_Wq0; o1 = g_Wq1; b -= 8192; }
    else               { in = Wk; o0 = g_Wk0; o1 = g_Wk1; b -= 9216; }
    int i = (b * 256 + threadIdx.x) * 4;
    float4 v = *(const float4*)(in + i);
    bf16 h0, l0, h1, l1, h2, l2, h3, l3;
    split2(v.x, h0, l0); split2(v.y, h1, l1);
    split2(v.z, h2, l2); split2(v.w, h3, l3);
    *(uint2*)(o0 + i) = make_uint2(pk(h0, h1), pk(h2, h3));
    *(uint2*)(o1 + i) = make_uint2(pk(l0, l1), pk(l2, l3));
}

// Transposed split of Wv only.
__global__ void tsplit_w(const float* __restrict__ Wv) {
    __shared__ float t[32][33];
    int k0 = blockIdx.y * 32, n0 = blockIdx.x * 32;
    int tx = threadIdx.x, ty = threadIdx.y;
#pragma unroll
    for (int i = 0; i < 4; i++)
        t[ty + 8 * i][tx] = Wv[(size_t)(k0 + ty + 8 * i) * DMODEL + n0 + tx];
    __syncthreads();
#pragma unroll
    for (int i = 0; i < 4; i++) {
        float v = t[tx][ty + 8 * i];
        bf16 h, l; split2(v, h, l);
        size_t o = (size_t)(n0 + ty + 8 * i) * DMODEL + k0 + tx;
        g_Wv0[o] = h; g_Wv1[o] = l;
    }
}

// w = Wk @ bq  (block e computes one dot)
__global__ void wvec_kernel(const float* __restrict__ Wk, const float* __restrict__ bq) {
    __shared__ float red[8];
    int e = blockIdx.x, tid = threadIdx.x;
    const float* row = Wk + (size_t)e * DMODEL;
    float s = 0.0f;
    for (int i = tid; i < DMODEL; i += 256) s += row[i] * bq[i];
#pragma unroll
    for (int o = 16; o; o >>= 1) s += __shfl_xor_sync(~0u, s, o);
    if ((tid & 31) == 0) red[tid >> 5] = s;
    __syncthreads();
    if (tid < 32) {
        float v = (tid < 8) ? red[tid] : 0.0f;
#pragma unroll
        for (int o = 4; o; o >>= 1) v += __shfl_xor_sync(~0u, v, o);
        if (tid == 0) g_w[e] = v;
    }
}

// c = z @ w  (block n computes one dot)
__global__ void cvec_kernel(const float* __restrict__ z) {
    __shared__ float red[8];
    int n = blockIdx.x, tid = threadIdx.x;
    const float* row = z + (size_t)n * DMODEL;
    float s = 0.0f;
    for (int i = tid; i < DMODEL; i += 256) s += row[i] * g_w[i];
#pragma unroll
    for (int o = 16; o; o >>= 1) s += __shfl_xor_sync(~0u, s, o);
    if ((tid & 31) == 0) red[tid >> 5] = s;
    __syncthreads();
    if (tid < 32) {
        float v = (tid < 8) ? red[tid] : 0.0f;
#pragma unroll
        for (int o = 4; o; o >>= 1) v += __shfl_xor_sync(~0u, v, o);
        if (tid == 0) g_c[n] = v;
    }
}

// ---------------- mma.sync GEMM core (R14 configuration — proven best) ------
#define GT 128
#define STG 49152u
#define OFF_AL 16384u
#define OFF_BH 32768u
#define OFF_BL 40960u
#define SMEM_SZ (2u * STG)

__device__ __forceinline__ void gemm_core(
    const bf16* __restrict__ A0, const bf16* __restrict__ A1,
    const bf16* __restrict__ B0, const bf16* __restrict__ B1,
    int Ktot, int kstart, int m0, int n0,
    float* __restrict__ Cf, bf16* __restrict__ C0, bf16* __restrict__ C1,
    const float* __restrict__ bias, int bias_mode, int ldc)
{
    extern __shared__ char smem[];
    const uint32_t dataB = s2u(smem);
    const int tid = threadIdx.x;
    const int lane = tid & 31, wid = tid >> 5;
    const int wm = (wid >> 1) * 64;
    const int wn = (wid & 1) * 32;

    const int S = (Ktot - kstart) >> 6;

    auto issue = [&](int s) {
        const uint32_t st = dataB + (uint32_t)(s & 1) * STG;
        const size_t kbase = (size_t)kstart + ((size_t)s << 6);
#pragma unroll
        for (int t = 0; t < 8; t++) {
            int chunk = tid + t * 128;
            int row = chunk >> 3, cc = chunk & 7;
            uint32_t so = swz(row, cc << 4);
            size_t go = kbase + (size_t)cc * 8;
            cp16(st + so,          A0 + (size_t)(m0 + row) * Ktot + go);
            cp16(st + OFF_AL + so, A1 + (size_t)(m0 + row) * Ktot + go);
        }
#pragma unroll
        for (int t = 0; t < 4; t++) {
            int chunk = tid + t * 128;
            int row = chunk >> 3, cc = chunk & 7;
            uint32_t so = swz(row, cc << 4);
            size_t go = kbase + (size_t)cc * 8;
            cp16(st + OFF_BH + so, B0 + (size_t)(n0 + row) * Ktot + go);
            cp16(st + OFF_BL + so, B1 + (size_t)(n0 + row) * Ktot + go);
        }
        cp_commit();
    };

    float acc[4][4][4];
#pragma unroll
    for (int i = 0; i < 4; i++)
#pragma unroll
        for (int j = 0; j < 4; j++)
#pragma unroll
            for (int q = 0; q < 4; q++) acc[i][j][q] = 0.0f;

    issue(0);
    if (S > 1) issue(1); else cp_commit();

    const int a_r  = (lane & 15);
    const int a_kb = (lane >> 4) << 4;
    const int b_r  = (lane & 7) + ((lane >> 4) << 3);
    const int b_kb = ((lane >> 3) & 1) << 4;

    for (int s = 0; s < S; s++) {
        cp_wait<1>();
        __syncthreads();
        const uint32_t st = dataB + (uint32_t)(s & 1) * STG;
        const uint32_t tAh = st, tAl = st + OFF_AL, tBh = st + OFF_BH, tBl = st + OFF_BL;

#pragma unroll
        for (int ks = 0; ks < 4; ks++) {
            const int kb = ks << 5;
            uint32_t ah[4][4], al[4][4];
#pragma unroll
            for (int i = 0; i < 4; i++) {
                int r = wm + 16 * i + a_r;
                uint32_t so = swz(r, kb + a_kb);
                ldsm_x4(ah[i], tAh + so);
                ldsm_x4(al[i], tAl + so);
            }
            uint32_t bh[4][2], bl[4][2];
#pragma unroll
            for (int j2 = 0; j2 < 2; j2++) {
                int r = wn + 16 * j2 + b_r;
                uint32_t so = swz(r, kb + b_kb);
                uint32_t t0[4], t1[4];
                ldsm_x4(t0, tBh + so);
                ldsm_x4(t1, tBl + so);
                bh[2*j2][0] = t0[0]; bh[2*j2][1] = t0[1];
                bh[2*j2+1][0] = t0[2]; bh[2*j2+1][1] = t0[3];
                bl[2*j2][0] = t1[0]; bl[2*j2][1] = t1[1];
                bl[2*j2+1][0] = t1[2]; bl[2*j2+1][1] = t1[3];
            }
#pragma unroll
            for (int i = 0; i < 4; i++)
#pragma unroll
                for (int j = 0; j < 4; j++) {
                    mma16816(acc[i][j], ah[i], bh[j][0], bh[j][1]);
                    mma16816(acc[i][j], ah[i], bl[j][0], bl[j][1]);
                    mma16816(acc[i][j], al[i], bh[j][0], bh[j][1]);
                }
        }
        __syncthreads();
        if (s + 2 < S) issue(s + 2); else cp_commit();
    }

    const int rbase = m0 + wm + (lane >> 2);
    const int cbase = n0 + wn + 2 * (lane & 3);
#pragma unroll
    for (int i = 0; i < 4; i++) {
        const int mlo = rbase + 16 * i, mhi = mlo + 8;
        float blo = 0.0f, bhi = 0.0f;
        if (bias_mode == 2) { blo = bias[mlo]; bhi = bias[mhi]; }
#pragma unroll
        for (int j = 0; j < 4; j++) {
            const int c = cbase + 8 * j;
            float d0 = acc[i][j][0], d1 = acc[i][j][1];
            float d2 = acc[i][j][2], d3 = acc[i][j][3];
            if (bias_mode == 1) {
                float b0 = __ldg(bias + c), b1 = __ldg(bias + c + 1);
                d0 += b0; d1 += b1; d2 += b0; d3 += b1;
            } else if (bias_mode == 2) {
                d0 += blo; d1 += blo; d2 += bhi; d3 += bhi;
            }
            if (C0) {
                bf16 h0, l0, h1, l1;
                split2(d0, h0, l0); split2(d1, h1, l1);
                *(uint32_t*)(C0 + (size_t)mlo * ldc + c) = pk(h0, h1);
                *(uint32_t*)(C1 + (size_t)mlo * ldc + c) = pk(l0, l1);
                split2(d2, h0, l0); split2(d3, h1, l1);
                *(uint32_t*)(C0 + (size_t)mhi * ldc + c) = pk(h0, h1);
                *(uint32_t*)(C1 + (size_t)mhi * ldc + c) = pk(l0, l1);
            } else {
                *(float2*)(Cf + (size_t)mlo * ldc + c) = make_float2(d0, d1);
                *(float2*)(Cf + (size_t)mhi * ldc + c) = make_float2(d2, d3);
            }
        }
    }
}

// Generic wrapper (QK tri grid / dense grids)
__global__ __launch_bounds__(GT, 2)
void gemm_bf16x3(const bf16* __restrict__ A0, const bf16* __restrict__ A1,
                 const bf16* __restrict__ B0, const bf16* __restrict__ B1,
                 int Ktot, int kstart_rb, int tri_mode,
                 float* __restrict__ Cf, bf16* __restrict__ C0, bf16* __restrict__ C1,
                 const float* __restrict__ bias, int bias_mode, int ldc)
{
    int m0, n0;
    if (tri_mode) {
        int bid = blockIdx.x, rb = 0;
        while (bid >= 64 - 2 * rb) { bid -= 64 - 2 * rb; rb++; }
        m0 = rb * 128; n0 = (2 * rb + bid) * 64;
    } else {
        m0 = blockIdx.y * 128; n0 = blockIdx.x * 64;
    }
    gemm_core(A0, A1, B0, B1, Ktot, kstart_rb ? m0 : 0, m0, n0,
              Cf, C0, C1, bias, bias_mode, ldc);
}

// Fused launch: MT = (WqWk^T)^T (128 CTAs) + VT = (zWv + bv)^T (512 CTAs)
__global__ __launch_bounds__(GT, 2)
void mtvt_kernel(const float* __restrict__ bv)
{
    int bid = blockIdx.x;
    if (bid < 128) {
        // MT[e][d] = sum_i Wk[e,i] Wq[d,i]  (A = Wk rows e, B = Wq rows d)
        int m0 = (bid >> 4) * 128, n0 = (bid & 15) * 64;
        gemm_core(g_Wk0, g_Wk1, g_Wq0, g_Wq1, DMODEL, 0, m0, n0,
                  nullptr, g_MT0, g_MT1, nullptr, 0, DMODEL);
    } else {
        bid -= 128;
        int m0 = (bid >> 6) * 128, n0 = (bid & 63) * 64;
        gemm_core(g_Wv0, g_Wv1, g_z0, g_z1, DMODEL, 0, m0, n0,
                  nullptr, g_VT0, g_VT1, bv, 2, LSEQ);
    }
}

// ---------------- softmax + P split (with column bias c) ---------------------
__global__ void softmax_kernel() {
    __shared__ float srow[LSEQ];
    __shared__ float red[16];
    __shared__ float bc;
    const int i = blockIdx.x;
    const float* row = g_S + (size_t)i * LSEQ;
    const int tid = threadIdx.x;
    const float sc = 0.03125f;

    float m = -INFINITY;
    for (int j = i + tid; j < LSEQ; j += 512) {
        float v = row[j] + __ldg(&g_c[j]);
        srow[j] = v; m = fmaxf(m, v);
    }
#pragma unroll
    for (int o = 16; o; o >>= 1) m = fmaxf(m, __shfl_xor_sync(~0u, m, o));
    if ((tid & 31) == 0) red[tid >> 5] = m;
    __syncthreads();
    if (tid < 32) {
        float v = (tid < 16) ? red[tid] : -INFINITY;
#pragma unroll
        for (int o = 8; o; o >>= 1) v = fmaxf(v, __shfl_xor_sync(~0u, v, o));
        if (tid == 0) bc = v;
    }
    __syncthreads();
    m = bc;
    __syncthreads();

    float s = 0.0f;
    for (int j = i + tid; j < LSEQ; j += 512) {
        float e = __expf((srow[j] - m) * sc);
        srow[j] = e; s += e;
    }
#pragma unroll
    for (int o = 16; o; o >>= 1) s += __shfl_xor_sync(~0u, s, o);
    if ((tid & 31) == 0) red[tid >> 5] = s;
    __syncthreads();
    if (tid < 32) {
        float v = (tid < 16) ? red[tid] : 0.0f;
#pragma unroll
        for (int o = 8; o; o >>= 1) v += __shfl_xor_sync(~0u, v, o);
        if (tid == 0) bc = v;
    }
    __syncthreads();
    const float inv = 1.0f / bc;

    const int rowstart = i & ~127;
    bf16* p0 = g_P0 + (size_t)i * LSEQ;
    bf16* p1 = g_P1 + (size_t)i * LSEQ;
    for (int j = rowstart + tid; j < LSEQ; j += 512) {
        float v = (j < i) ? 0.0f : srow[j] * inv;
        bf16 h, l; split2(v, h, l);
        p0[j] = h; p1[j] = l;
    }
}

// ---------------- launch -----------------------------------------------------
extern "C" void kernel_launch(void* const* d_in, const int* in_sizes, int n_in,
                              void* d_out, int out_size)
{
    const float* x  = (const float*)d_in[0];
    const float* z  = (const float*)d_in[1];
    const float* Wq = (const float*)d_in[2];
    const float* bq = (const float*)d_in[3];
    const float* Wk = (const float*)d_in[4];
    const float* bk = (const float*)d_in[5];   // row-term: cancels in softmax
    const float* Wv = (const float*)d_in[6];
    const float* bv = (const float*)d_in[7];
    (void)bk;
    float* out = (float*)d_out;

    cudaFuncSetAttribute(gemm_bf16x3, cudaFuncAttributeMaxDynamicSharedMemorySize, SMEM_SZ);
    cudaFuncSetAttribute(mtvt_kernel, cudaFuncAttributeMaxDynamicSharedMemorySize, SMEM_SZ);

    bf16 *x0, *x1, *z0, *z1, *mt0, *mt1, *gg0, *gg1, *vt0, *vt1, *p0, *p1;
    float* S;
    cudaGetSymbolAddress((void**)&x0, g_x0);   cudaGetSymbolAddress((void**)&x1, g_x1);
    cudaGetSymbolAddress((void**)&z0, g_z0);   cudaGetSymbolAddress((void**)&z1, g_z1);
    cudaGetSymbolAddress((void**)&mt0, g_MT0); cudaGetSymbolAddress((void**)&mt1, g_MT1);
    cudaGetSymbolAddress((void**)&gg0, g_G0);  cudaGetSymbolAddress((void**)&gg1, g_G1);
    cudaGetSymbolAddress((void**)&vt0, g_VT0); cudaGetSymbolAddress((void**)&vt1, g_VT1);
    cudaGetSymbolAddress((void**)&p0, g_P0);   cudaGetSymbolAddress((void**)&p1, g_P1);
    cudaGetSymbolAddress((void**)&S, g_S);

    split_f32<<<10240, 256>>>(x, z, Wq, Wk);
    tsplit_w<<<dim3(32, 32), dim3(32, 8)>>>(Wv);
    wvec_kernel<<<DMODEL, 256>>>(Wk, bq);
    cvec_kernel<<<LSEQ, 256>>>(z);

    // MT = (Wq Wk^T)^T and VT = (z Wv + bv)^T in one 640-CTA launch
    mtvt_kernel<<<640, GT, SMEM_SZ>>>(bv);

    // G = x @ M  (B operand = MT, K-major), split output
    gemm_bf16x3<<<dim3(16, 32), GT, SMEM_SZ>>>(x0, x1, mt0, mt1, DMODEL, 0, 0,
                                               nullptr, gg0, gg1, nullptr, 0, DMODEL);

    // S = G @ z^T  (compact triangular grid; K-proj eliminated)
    gemm_bf16x3<<<dim3(1056, 1), GT, SMEM_SZ>>>(gg0, gg1, z0, z1, DMODEL, 0, 1,
                                                S, nullptr, nullptr, nullptr, 0, LSEQ);
    softmax_kernel<<<LSEQ, 512>>>();
    // O = P @ V  (k starts at row-block diagonal)
    gemm_bf16x3<<<dim3(16, 32), GT, SMEM_SZ>>>(p0, p1, vt0, vt1, LSEQ, 1, 0,
                                               out, nullptr, nullptr, nullptr, 0, DMODEL);
}